// round 2
// baseline (speedup 1.0000x reference)
#include <cuda_runtime.h>
#include <cstdint>

// Problem constants
#define NB    32
#define HIN   64
#define WIN   64
#define T_IN  8
#define A_INP 16
#define T_OUT 8
#define A_OUT 32
#define HC    32
#define WC    32
// pixels = NB*HC*WC = 32768

// ---------- packed f32x2 helpers (Blackwell sm_100+) ----------
__device__ __forceinline__ unsigned long long pack2(float lo, float hi) {
    unsigned long long r;
    asm("mov.b64 %0, {%1, %2};" : "=l"(r) : "f"(lo), "f"(hi));
    return r;
}
__device__ __forceinline__ void unpack2(unsigned long long v, float& lo, float& hi) {
    asm("mov.b64 {%0, %1}, %2;" : "=f"(lo), "=f"(hi) : "l"(v));
}
__device__ __forceinline__ unsigned long long ffma2(unsigned long long a,
                                                    unsigned long long b,
                                                    unsigned long long c) {
    unsigned long long d;
    asm("fma.rn.f32x2 %0, %1, %2, %3;" : "=l"(d) : "l"(a), "l"(b), "l"(c));
    return d;
}

// One warp per output pixel. Lane mapping: to = lane>>2, q = lane&3,
// lane owns a = [q*8, q*8+8) of output capsule `to`.
__global__ __launch_bounds__(256)
void capsule_fused_kernel(const float* __restrict__ x,
                          const float* __restrict__ kern,   // [T_IN][2][2][1][256]
                          const float* __restrict__ bias,   // [1][1][8][32]
                          float* __restrict__ out)          // [B][32][32][8][32]
{
    __shared__ __align__(16) float Ksh[T_IN * 4 * 256];  // [ti][p][to*32+a]
    __shared__ __align__(16) float bias_sh[256];
    __shared__ float4 xs4_sh[8][T_IN];                   // [warp][ti] -> 4 window sums

    const int tid = threadIdx.x;

    // Stage K (8192 floats) + bias (256 floats) into shared
    {
        const float4* src = (const float4*)kern;
        float4* dst = (float4*)Ksh;
#pragma unroll
        for (int k = 0; k < 8; k++) dst[tid + 256 * k] = src[tid + 256 * k];
        if (tid < 64) ((float4*)bias_sh)[tid] = ((const float4*)bias)[tid];
    }
    __syncthreads();

    const int warp = tid >> 5;
    const int lane = tid & 31;
    const int pix  = blockIdx.x * 8 + warp;
    const int b = pix >> 10;
    const int i = (pix >> 5) & 31;
    const int j = pix & 31;

    // ---------------- Phase 1: window channel-sums xs[ti][p] ----------------
    // lane -> (p = lane>>3, ti = lane&7); each lane sums 16 floats of x.
    {
        const int p  = lane >> 3;
        const int ti = lane & 7;
        const int h  = 2 * i + (p >> 1);
        const int w  = 2 * j + (p & 1);
        const float4* xp =
            (const float4*)(x + ((((size_t)b * HIN + h) * WIN + w) * T_IN + ti) * A_INP);
        float4 s0 = xp[0], s1 = xp[1], s2 = xp[2], s3 = xp[3];
        float s = (s0.x + s0.y + s0.z + s0.w) + (s1.x + s1.y + s1.z + s1.w) +
                  (s2.x + s2.y + s2.z + s2.w) + (s3.x + s3.y + s3.z + s3.w);
        ((float*)xs4_sh)[warp * 32 + ti * 4 + p] = s;
    }
    __syncwarp();

    const int to   = lane >> 2;
    const int q    = lane & 3;
    const int coff = to * 32 + q * 8;   // column offset in [0,256)

    // ---------------- Phase 2: votes v[ti][8 a's] as 4 packed pairs --------
    unsigned long long v2[T_IN][4];
#pragma unroll
    for (int ti = 0; ti < T_IN; ti++) {
        float4 xs = xs4_sh[warp][ti];
        float xsp[4] = {xs.x, xs.y, xs.z, xs.w};
        const float4* kp = (const float4*)&Ksh[(ti * 4) * 256 + coff];
        unsigned long long a0 = 0ull, a1 = 0ull, a2 = 0ull, a3 = 0ull;
#pragma unroll
        for (int p = 0; p < 4; p++) {
            unsigned long long xs2 = pack2(xsp[p], xsp[p]);
            float4 k0 = kp[p * 64];        // stride between p slices = 256 floats
            float4 k1 = kp[p * 64 + 1];
            a0 = ffma2(xs2, pack2(k0.x, k0.y), a0);
            a1 = ffma2(xs2, pack2(k0.z, k0.w), a1);
            a2 = ffma2(xs2, pack2(k1.x, k1.y), a2);
            a3 = ffma2(xs2, pack2(k1.z, k1.w), a3);
        }
        v2[ti][0] = a0; v2[ti][1] = a1; v2[ti][2] = a2; v2[ti][3] = a3;
    }

    // bias pairs for this lane's 8 outputs
    unsigned long long bias2[4];
    {
        const float4* bp = (const float4*)&bias_sh[coff];
        float4 b0 = bp[0], b1 = bp[1];
        bias2[0] = pack2(b0.x, b0.y); bias2[1] = pack2(b0.z, b0.w);
        bias2[2] = pack2(b1.x, b1.y); bias2[3] = pack2(b1.z, b1.w);
    }

    // ---------------- Phase 3: dynamic routing (3 iters) -------------------
    float logit[T_IN];
#pragma unroll
    for (int ti = 0; ti < T_IN; ti++) logit[ti] = 0.0f;

    unsigned long long act2[4];

#pragma unroll
    for (int r = 0; r < 3; r++) {
        unsigned long long pre2[4] = {bias2[0], bias2[1], bias2[2], bias2[3]};
        // softmax over `to` (spread across lanes with stride 4) + preact accum
#pragma unroll
        for (int ti = 0; ti < T_IN; ti++) {
            float m = logit[ti];
            m = fmaxf(m, __shfl_xor_sync(0xffffffffu, m, 4));
            m = fmaxf(m, __shfl_xor_sync(0xffffffffu, m, 8));
            m = fmaxf(m, __shfl_xor_sync(0xffffffffu, m, 16));
            float e = __expf(logit[ti] - m);
            float s = e;
            s += __shfl_xor_sync(0xffffffffu, s, 4);
            s += __shfl_xor_sync(0xffffffffu, s, 8);
            s += __shfl_xor_sync(0xffffffffu, s, 16);
            float route = __fdividef(e, s);
            unsigned long long r2 = pack2(route, route);
#pragma unroll
            for (int k = 0; k < 4; k++) pre2[k] = ffma2(r2, v2[ti][k], pre2[k]);
        }
        // squash: n2 over all 32 a's = in-lane 8 + reduce over 4 lanes (same to)
        float n2 = 0.0f;
#pragma unroll
        for (int k = 0; k < 4; k++) {
            float lo, hi; unpack2(pre2[k], lo, hi);
            n2 += lo * lo + hi * hi;
        }
        n2 += __shfl_xor_sync(0xffffffffu, n2, 1);
        n2 += __shfl_xor_sync(0xffffffffu, n2, 2);
        float scale = __fdividef(sqrtf(n2), 1.0f + n2);
        unsigned long long sc2 = pack2(scale, scale);
#pragma unroll
        for (int k = 0; k < 4; k++) act2[k] = ffma2(sc2, pre2[k], 0ull);

        // logit update (dead on the final iteration -> skipped)
        if (r < 2) {
#pragma unroll
            for (int ti = 0; ti < T_IN; ti++) {
                unsigned long long d2;
                d2 = ffma2(v2[ti][0], act2[0], 0ull);
                d2 = ffma2(v2[ti][1], act2[1], d2);
                d2 = ffma2(v2[ti][2], act2[2], d2);
                d2 = ffma2(v2[ti][3], act2[3], d2);
                float lo, hi; unpack2(d2, lo, hi);
                float d = lo + hi;
                d += __shfl_xor_sync(0xffffffffu, d, 1);
                d += __shfl_xor_sync(0xffffffffu, d, 2);
                logit[ti] += d;
            }
        }
    }

    // ---------------- Write activation -------------------------------------
    float* op = out + ((((size_t)b * HC + i) * WC + j) * T_OUT + to) * A_OUT + q * 8;
    float4 o0, o1;
    unpack2(act2[0], o0.x, o0.y); unpack2(act2[1], o0.z, o0.w);
    unpack2(act2[2], o1.x, o1.y); unpack2(act2[3], o1.z, o1.w);
    ((float4*)op)[0] = o0;
    ((float4*)op)[1] = o1;
}

extern "C" void kernel_launch(void* const* d_in, const int* in_sizes, int n_in,
                              void* d_out, int out_size) {
    const float* x    = (const float*)d_in[0];
    const float* kern = (const float*)d_in[1];
    const float* bias = (const float*)d_in[2];
    float* out = (float*)d_out;
    // 32768 pixels, 8 warps (pixels) per 256-thread block
    capsule_fused_kernel<<<4096, 256>>>(x, kern, bias, out);
}

// round 4
// speedup vs baseline: 1.3171x; 1.3171x over previous
#include <cuda_runtime.h>
#include <cstdint>

// Problem constants
#define NB    32
#define HIN   64
#define WIN   64
#define T_IN  8
#define A_INP 16
#define T_OUT 8
#define A_OUT 32
#define HC    32
#define WC    32
// pixels = NB*HC*WC = 32768; 2 pixels/warp, 8 warps/block -> 16 px/block, 2048 blocks

// ---------- packed f32x2 helpers (Blackwell sm_100+) ----------
__device__ __forceinline__ unsigned long long pack2(float lo, float hi) {
    unsigned long long r;
    asm("mov.b64 %0, {%1, %2};" : "=l"(r) : "f"(lo), "f"(hi));
    return r;
}
__device__ __forceinline__ void unpack2(unsigned long long v, float& lo, float& hi) {
    asm("mov.b64 {%0, %1}, %2;" : "=f"(lo), "=f"(hi) : "l"(v));
}
__device__ __forceinline__ unsigned long long ffma2(unsigned long long a,
                                                    unsigned long long b,
                                                    unsigned long long c) {
    unsigned long long d;
    asm("fma.rn.f32x2 %0, %1, %2, %3;" : "=l"(d) : "l"(a), "l"(b), "l"(c));
    return d;
}

// Lane mapping inside routing: to = lane>>2, q = lane&3; lane owns a=[q*8,q*8+8) of capsule to.
__global__ __launch_bounds__(256, 1)
void capsule_fused_kernel(const float* __restrict__ x,
                          const float* __restrict__ kern,   // [T_IN][2][2][1][256]
                          const float* __restrict__ bias,   // [1][1][8][32]
                          float* __restrict__ out)          // [B][32][32][8][32]
{
    // Permuted K: Kperm[ti][p][half][lane][4]  (lane = to*4+q, half selects a-sub-quad)
    // -> every warp-wide LDS.128 in the votes loop is a contiguous 512B segment (conflict-free).
    __shared__ __align__(16) float Kperm[T_IN * 4 * 2 * 32 * 4];   // 32 KB
    __shared__ __align__(16) float bias_sh[256];                   // 1 KB
    __shared__ float xs_sh[8][2][T_IN][4];                         // [warp][px][ti][p], 2 KB

    const int tid = threadIdx.x;

    // ---- Stage K into permuted shared layout + bias ----
    {
#pragma unroll
        for (int r = 0; r < 8; r++) {
            int d = tid + 256 * r;              // dest float4 index in [0,2048)
            int ti   = d >> 8;
            int p    = (d >> 6) & 3;
            int half = (d >> 5) & 1;
            int ln   = d & 31;
            // source float4 index: floats ti*1024 + p*256 + (ln>>2)*32 + (ln&3)*8 + half*4
            int s = ti * 256 + p * 64 + (ln >> 2) * 8 + (ln & 3) * 2 + half;
            ((float4*)Kperm)[d] = ((const float4*)kern)[s];
        }
        if (tid < 64) ((float4*)bias_sh)[tid] = ((const float4*)bias)[tid];
    }
    __syncthreads();

    const int warp = tid >> 5;
    const int lane = tid & 31;
    const int gp0  = blockIdx.x * 16 + warp * 2;  // first pixel of this warp's pair

    // ---------------- Phase 1: window channel-sums xs[px][ti][p] ------------
    // 64 tasks (2 px * 4 p * 8 ti); lane does (px=0) and (px=1) with same (p,ti).
    {
        const int p  = lane >> 3;
        const int ti = lane & 7;
#pragma unroll
        for (int px = 0; px < 2; px++) {
            const int gp = gp0 + px;
            const int b = gp >> 10;
            const int i = (gp >> 5) & 31;
            const int j = gp & 31;
            const int h = 2 * i + (p >> 1);
            const int w = 2 * j + (p & 1);
            const float4* xp =
                (const float4*)(x + ((((size_t)b * HIN + h) * WIN + w) * T_IN + ti) * A_INP);
            float4 s0 = xp[0], s1 = xp[1], s2 = xp[2], s3 = xp[3];
            float s = (s0.x + s0.y + s0.z + s0.w) + (s1.x + s1.y + s1.z + s1.w) +
                      (s2.x + s2.y + s2.z + s2.w) + (s3.x + s3.y + s3.z + s3.w);
            xs_sh[warp][px][ti][p] = s;
        }
    }
    __syncwarp();

    const int to   = lane >> 2;
    const int q    = lane & 3;
    const int coff = to * 32 + q * 8;   // column offset in [0,256) (original layout)

    // ---------------- Phase 2: votes for BOTH pixels, K read once ----------
    unsigned long long v2[2][T_IN][4];
#pragma unroll
    for (int px = 0; px < 2; px++)
#pragma unroll
        for (int ti = 0; ti < T_IN; ti++)
#pragma unroll
            for (int k = 0; k < 4; k++) v2[px][ti][k] = 0ull;

#pragma unroll
    for (int ti = 0; ti < T_IN; ti++) {
#pragma unroll
        for (int p = 0; p < 4; p++) {
            const float* kb = &Kperm[(ti * 4 + p) * 256 + lane * 4];
            float4 k0 = *(const float4*)kb;          // half 0 (contiguous 512B across warp)
            float4 k1 = *(const float4*)(kb + 128);  // half 1
            unsigned long long kp0 = pack2(k0.x, k0.y);
            unsigned long long kp1 = pack2(k0.z, k0.w);
            unsigned long long kp2 = pack2(k1.x, k1.y);
            unsigned long long kp3 = pack2(k1.z, k1.w);
#pragma unroll
            for (int px = 0; px < 2; px++) {
                float s = xs_sh[warp][px][ti][p];     // broadcast LDS
                unsigned long long s2 = pack2(s, s);
                v2[px][ti][0] = ffma2(s2, kp0, v2[px][ti][0]);
                v2[px][ti][1] = ffma2(s2, kp1, v2[px][ti][1]);
                v2[px][ti][2] = ffma2(s2, kp2, v2[px][ti][2]);
                v2[px][ti][3] = ffma2(s2, kp3, v2[px][ti][3]);
            }
        }
    }

    // bias pairs for this lane's 8 outputs
    unsigned long long bias2[4];
    {
        const float4* bp = (const float4*)&bias_sh[coff];
        float4 b0 = bp[0], b1 = bp[1];
        bias2[0] = pack2(b0.x, b0.y); bias2[1] = pack2(b0.z, b0.w);
        bias2[2] = pack2(b1.x, b1.y); bias2[3] = pack2(b1.z, b1.w);
    }

    // ---------------- Phase 3: dynamic routing (3 iters), per pixel --------
#pragma unroll
    for (int px = 0; px < 2; px++) {
        float logit[T_IN];
#pragma unroll
        for (int ti = 0; ti < T_IN; ti++) logit[ti] = 0.0f;

        unsigned long long act2[4];

#pragma unroll
        for (int r = 0; r < 3; r++) {
            unsigned long long pre2[4] = {bias2[0], bias2[1], bias2[2], bias2[3]};
            // softmax over `to` (to spread across lanes with stride 4)
#pragma unroll
            for (int ti = 0; ti < T_IN; ti++) {
                float m = logit[ti];
                m = fmaxf(m, __shfl_xor_sync(0xffffffffu, m, 4));
                m = fmaxf(m, __shfl_xor_sync(0xffffffffu, m, 8));
                m = fmaxf(m, __shfl_xor_sync(0xffffffffu, m, 16));
                float e = __expf(logit[ti] - m);
                float s = e;
                s += __shfl_xor_sync(0xffffffffu, s, 4);
                s += __shfl_xor_sync(0xffffffffu, s, 8);
                s += __shfl_xor_sync(0xffffffffu, s, 16);
                float route = __fdividef(e, s);
                unsigned long long r2 = pack2(route, route);
#pragma unroll
                for (int k = 0; k < 4; k++) pre2[k] = ffma2(r2, v2[px][ti][k], pre2[k]);
            }
            // squash: norm over 32 a's = in-lane 8 + reduce over 4 lanes (same to)
            float n2 = 0.0f;
#pragma unroll
            for (int k = 0; k < 4; k++) {
                float lo, hi; unpack2(pre2[k], lo, hi);
                n2 += lo * lo + hi * hi;
            }
            n2 += __shfl_xor_sync(0xffffffffu, n2, 1);
            n2 += __shfl_xor_sync(0xffffffffu, n2, 2);
            float scale = __fdividef(sqrtf(n2), 1.0f + n2);
            unsigned long long sc2 = pack2(scale, scale);
#pragma unroll
            for (int k = 0; k < 4; k++) act2[k] = ffma2(sc2, pre2[k], 0ull);

            // logit update (dead on the final iteration -> skipped)
            if (r < 2) {
#pragma unroll
                for (int ti = 0; ti < T_IN; ti++) {
                    unsigned long long d2;
                    d2 = ffma2(v2[px][ti][0], act2[0], 0ull);
                    d2 = ffma2(v2[px][ti][1], act2[1], d2);
                    d2 = ffma2(v2[px][ti][2], act2[2], d2);
                    d2 = ffma2(v2[px][ti][3], act2[3], d2);
                    float lo, hi; unpack2(d2, lo, hi);
                    float d = lo + hi;
                    d += __shfl_xor_sync(0xffffffffu, d, 1);
                    d += __shfl_xor_sync(0xffffffffu, d, 2);
                    logit[ti] += d;
                }
            }
        }

        // ---- Write activation for this pixel ----
        const int gp = gp0 + px;
        float* op = out + (size_t)gp * (T_OUT * A_OUT) + coff;
        float4 o0, o1;
        unpack2(act2[0], o0.x, o0.y); unpack2(act2[1], o0.z, o0.w);
        unpack2(act2[2], o1.x, o1.y); unpack2(act2[3], o1.z, o1.w);
        ((float4*)op)[0] = o0;
        ((float4*)op)[1] = o1;
    }
}

extern "C" void kernel_launch(void* const* d_in, const int* in_sizes, int n_in,
                              void* d_out, int out_size) {
    const float* x    = (const float*)d_in[0];
    const float* kern = (const float*)d_in[1];
    const float* bias = (const float*)d_in[2];
    float* out = (float*)d_out;
    // 32768 pixels, 16 pixels per 256-thread block (2 per warp)
    capsule_fused_kernel<<<2048, 256>>>(x, kern, bias, out);
}

// round 6
// speedup vs baseline: 1.6325x; 1.2395x over previous
#include <cuda_runtime.h>
#include <cstdint>

// Problem constants
#define NB    32
#define HIN   64
#define WIN   64
#define T_IN  8
#define A_INP 16
#define T_OUT 8
#define A_OUT 32
#define HC    32
#define WC    32
// pixels = 32768; 2 px/warp, 4 warps/block -> 8 px/block, 4096 blocks

// ---------- packed f32x2 helpers (Blackwell sm_100+) ----------
__device__ __forceinline__ unsigned long long pack2(float lo, float hi) {
    unsigned long long r;
    asm("mov.b64 %0, {%1, %2};" : "=l"(r) : "f"(lo), "f"(hi));
    return r;
}
__device__ __forceinline__ void unpack2(unsigned long long v, float& lo, float& hi) {
    asm("mov.b64 {%0, %1}, %2;" : "=f"(lo), "=f"(hi) : "l"(v));
}
__device__ __forceinline__ unsigned long long ffma2(unsigned long long a,
                                                    unsigned long long b,
                                                    unsigned long long c) {
    unsigned long long d;
    asm("fma.rn.f32x2 %0, %1, %2, %3;" : "=l"(d) : "l"(a), "l"(b), "l"(c));
    return d;
}

// Lane mapping in routing: to = lane>>2, q = lane&3; lane owns a=[q*8,q*8+8) of capsule to.
__global__ __launch_bounds__(128, 3)
void capsule_fused_kernel(const float* __restrict__ x,
                          const float* __restrict__ kern,   // [T_IN][2][2][1][256]
                          const float* __restrict__ bias,   // [1][1][8][32]
                          float* __restrict__ out)          // [B][32][32][8][32]
{
    // Permuted K: Kperm[ti][p][half][lane][4] -> warp-wide LDS.128 = contiguous 512B (conflict-free)
    __shared__ __align__(16) float Kperm[T_IN * 4 * 2 * 32 * 4];   // 32 KB
    __shared__ __align__(16) float bias_sh[256];                   // 1 KB
    __shared__ float xs_sh[4][2][T_IN][4];                         // [warp][px][ti][p]

    const int tid = threadIdx.x;

    // ---- Stage K into permuted shared layout + bias ----
    {
#pragma unroll
        for (int r = 0; r < 16; r++) {
            int d = tid + 128 * r;              // dest float4 index in [0,2048)
            int ti   = d >> 8;
            int p    = (d >> 6) & 3;
            int half = (d >> 5) & 1;
            int ln   = d & 31;
            int s = ti * 256 + p * 64 + (ln >> 2) * 8 + (ln & 3) * 2 + half;
            ((float4*)Kperm)[d] = ((const float4*)kern)[s];
        }
        if (tid < 64) ((float4*)bias_sh)[tid] = ((const float4*)bias)[tid];
    }
    __syncthreads();

    const int warp = tid >> 5;
    const int lane = tid & 31;
    const int gp0  = blockIdx.x * 8 + warp * 2;   // first pixel of this warp's pair

    // ---------------- Phase 1: window channel-sums xs[px][ti][p] ------------
    {
        const int p  = lane >> 3;
        const int ti = lane & 7;
#pragma unroll
        for (int px = 0; px < 2; px++) {
            const int gp = gp0 + px;
            const int b = gp >> 10;
            const int i = (gp >> 5) & 31;
            const int j = gp & 31;
            const int h = 2 * i + (p >> 1);
            const int w = 2 * j + (p & 1);
            const float4* xp =
                (const float4*)(x + ((((size_t)b * HIN + h) * WIN + w) * T_IN + ti) * A_INP);
            float4 s0 = xp[0], s1 = xp[1], s2 = xp[2], s3 = xp[3];
            float s = (s0.x + s0.y + s0.z + s0.w) + (s1.x + s1.y + s1.z + s1.w) +
                      (s2.x + s2.y + s2.z + s2.w) + (s3.x + s3.y + s3.z + s3.w);
            xs_sh[warp][px][ti][p] = s;
        }
    }
    __syncwarp();

    const int to   = lane >> 2;
    const int q    = lane & 3;
    const int coff = to * 32 + q * 8;   // column offset in [0,256)

    // ---------------- Phase 2: votes for BOTH pixels, K read once ----------
    unsigned long long v2[2][T_IN][4];
#pragma unroll
    for (int px = 0; px < 2; px++)
#pragma unroll
        for (int ti = 0; ti < T_IN; ti++)
#pragma unroll
            for (int k = 0; k < 4; k++) v2[px][ti][k] = 0ull;

#pragma unroll
    for (int ti = 0; ti < T_IN; ti++) {
#pragma unroll
        for (int p = 0; p < 4; p++) {
            const float* kb = &Kperm[(ti * 4 + p) * 256 + lane * 4];
            float4 k0 = *(const float4*)kb;          // half 0
            float4 k1 = *(const float4*)(kb + 128);  // half 1
            unsigned long long kp0 = pack2(k0.x, k0.y);
            unsigned long long kp1 = pack2(k0.z, k0.w);
            unsigned long long kp2 = pack2(k1.x, k1.y);
            unsigned long long kp3 = pack2(k1.z, k1.w);
#pragma unroll
            for (int px = 0; px < 2; px++) {
                float s = xs_sh[warp][px][ti][p];     // broadcast LDS
                unsigned long long s2 = pack2(s, s);
                v2[px][ti][0] = ffma2(s2, kp0, v2[px][ti][0]);
                v2[px][ti][1] = ffma2(s2, kp1, v2[px][ti][1]);
                v2[px][ti][2] = ffma2(s2, kp2, v2[px][ti][2]);
                v2[px][ti][3] = ffma2(s2, kp3, v2[px][ti][3]);
            }
        }
    }

    const float4* bp = (const float4*)&bias_sh[coff];

    // ---------------- Phase 3: dynamic routing (3 iters), per pixel --------
#pragma unroll
    for (int px = 0; px < 2; px++) {
        float logit[T_IN];
        unsigned long long act2[4];

        // ---- iteration 0: logits are all zero -> route == 1/8 exactly ----
        unsigned long long pre2[4];
        {
            float4 b0 = bp[0], b1 = bp[1];
            pre2[0] = pack2(b0.x, b0.y); pre2[1] = pack2(b0.z, b0.w);
            pre2[2] = pack2(b1.x, b1.y); pre2[3] = pack2(b1.z, b1.w);
        }
        const unsigned long long c8 = pack2(0.125f, 0.125f);
#pragma unroll
        for (int ti = 0; ti < T_IN; ti++)
#pragma unroll
            for (int k = 0; k < 4; k++) pre2[k] = ffma2(c8, v2[px][ti][k], pre2[k]);

        {   // squash
            float n2 = 0.0f;
#pragma unroll
            for (int k = 0; k < 4; k++) {
                float lo, hi; unpack2(pre2[k], lo, hi);
                n2 += lo * lo + hi * hi;
            }
            n2 += __shfl_xor_sync(0xffffffffu, n2, 1);
            n2 += __shfl_xor_sync(0xffffffffu, n2, 2);
            float scale = __fdividef(sqrtf(n2), 1.0f + n2);
            unsigned long long sc2 = pack2(scale, scale);
#pragma unroll
            for (int k = 0; k < 4; k++) act2[k] = ffma2(sc2, pre2[k], 0ull);
        }
        // logit after iter 0 = dot(votes, act)
#pragma unroll
        for (int ti = 0; ti < T_IN; ti++) {
            unsigned long long d2;
            d2 = ffma2(v2[px][ti][0], act2[0], 0ull);
            d2 = ffma2(v2[px][ti][1], act2[1], d2);
            d2 = ffma2(v2[px][ti][2], act2[2], d2);
            d2 = ffma2(v2[px][ti][3], act2[3], d2);
            float lo, hi; unpack2(d2, lo, hi);
            float d = lo + hi;
            d += __shfl_xor_sync(0xffffffffu, d, 1);
            d += __shfl_xor_sync(0xffffffffu, d, 2);
            logit[ti] = d;
        }

        // ---- iterations 1,2: softmax without max-subtraction (|logit| small) ----
#pragma unroll
        for (int r = 1; r < 3; r++) {
            {
                float4 b0 = bp[0], b1 = bp[1];
                pre2[0] = pack2(b0.x, b0.y); pre2[1] = pack2(b0.z, b0.w);
                pre2[2] = pack2(b1.x, b1.y); pre2[3] = pack2(b1.z, b1.w);
            }
#pragma unroll
            for (int ti = 0; ti < T_IN; ti++) {
                float e = __expf(logit[ti]);
                float s = e;
                s += __shfl_xor_sync(0xffffffffu, s, 4);
                s += __shfl_xor_sync(0xffffffffu, s, 8);
                s += __shfl_xor_sync(0xffffffffu, s, 16);
                float route = __fdividef(e, s);
                unsigned long long r2 = pack2(route, route);
#pragma unroll
                for (int k = 0; k < 4; k++) pre2[k] = ffma2(r2, v2[px][ti][k], pre2[k]);
            }
            float n2 = 0.0f;
#pragma unroll
            for (int k = 0; k < 4; k++) {
                float lo, hi; unpack2(pre2[k], lo, hi);
                n2 += lo * lo + hi * hi;
            }
            n2 += __shfl_xor_sync(0xffffffffu, n2, 1);
            n2 += __shfl_xor_sync(0xffffffffu, n2, 2);
            float scale = __fdividef(sqrtf(n2), 1.0f + n2);
            unsigned long long sc2 = pack2(scale, scale);
#pragma unroll
            for (int k = 0; k < 4; k++) act2[k] = ffma2(sc2, pre2[k], 0ull);

            if (r == 1) {   // final-iteration logit update is dead code
#pragma unroll
                for (int ti = 0; ti < T_IN; ti++) {
                    unsigned long long d2;
                    d2 = ffma2(v2[px][ti][0], act2[0], 0ull);
                    d2 = ffma2(v2[px][ti][1], act2[1], d2);
                    d2 = ffma2(v2[px][ti][2], act2[2], d2);
                    d2 = ffma2(v2[px][ti][3], act2[3], d2);
                    float lo, hi; unpack2(d2, lo, hi);
                    float d = lo + hi;
                    d += __shfl_xor_sync(0xffffffffu, d, 1);
                    d += __shfl_xor_sync(0xffffffffu, d, 2);
                    logit[ti] += d;
                }
            }
        }

        // ---- Write activation for this pixel ----
        const int gp = gp0 + px;
        float* op = out + (size_t)gp * (T_OUT * A_OUT) + coff;
        float4 o0, o1;
        unpack2(act2[0], o0.x, o0.y); unpack2(act2[1], o0.z, o0.w);
        unpack2(act2[2], o1.x, o1.y); unpack2(act2[3], o1.z, o1.w);
        ((float4*)op)[0] = o0;
        ((float4*)op)[1] = o1;
    }
}

extern "C" void kernel_launch(void* const* d_in, const int* in_sizes, int n_in,
                              void* d_out, int out_size) {
    const float* x    = (const float*)d_in[0];
    const float* kern = (const float*)d_in[1];
    const float* bias = (const float*)d_in[2];
    float* out = (float*)d_out;
    // 32768 pixels, 8 pixels per 128-thread block (2 per warp)
    capsule_fused_kernel<<<4096, 128>>>(x, kern, bias, out);
}